// round 16
// baseline (speedup 1.0000x reference)
#include <cuda_runtime.h>
#include <math.h>

#define BB 256
#define TT 512
#define SS 64
#define OO 128
#define HH 128
#define FH 512   // 4*H
#define LOG2PI 1.8378770664093453f

// scratch: xK = obs @ K_lstm + b_lstm   [B*T, 4H]
__device__ float g_xk[(size_t)BB * TT * FH];
__device__ double g_acc[2];   // [0] = sum kl, [1] = sum logp

__global__ void init_kernel() {
    g_acc[0] = 0.0;
    g_acc[1] = 0.0;
}

__global__ void finalize_kernel(float* out) {
    out[0] = (float)(g_acc[0] / (double)(BB * TT) - g_acc[1] / (double)BB);
}

// ---------------------------------------------------------------------------
// Kernel A: xK GEMM.  obs [B*T,128] @ K_lstm [128,512] + b_lstm -> g_xk
// BM=64, BN=128, K=128 (single chunk), 256 threads, 8x4 per thread.
// ---------------------------------------------------------------------------
__global__ void __launch_bounds__(256, 2) xk_gemm(
    const float* __restrict__ obs,
    const float* __restrict__ K,
    const float* __restrict__ bias)
{
    extern __shared__ float sm[];
    float* As = sm;                 // [64][128] row-major
    float* Bs = sm + 64 * 128;      // [128][128]  Bs[k][n]

    const int row0 = blockIdx.x * 64;
    const int col0 = blockIdx.y * 128;
    const int tid = threadIdx.x;

    // A tile: rows row0..row0+63 are contiguous in obs (row stride 128)
    for (int i = tid * 4; i < 64 * 128; i += 256 * 4) {
        *(float4*)&As[i] = *(const float4*)&obs[(size_t)row0 * 128 + i];
    }
    // B tile
    for (int i = tid * 4; i < 128 * 128; i += 256 * 4) {
        int k = i >> 7;
        int n = i & 127;
        *(float4*)&Bs[i] = *(const float4*)&K[(size_t)k * FH + col0 + n];
    }
    __syncthreads();

    const int ty = tid >> 5;   // 0..7  -> 8 rows each
    const int tx = tid & 31;   // 0..31 -> 4 cols each

    float acc[8][4];
#pragma unroll
    for (int i = 0; i < 8; i++)
#pragma unroll
        for (int j = 0; j < 4; j++) acc[i][j] = 0.f;

#pragma unroll 4
    for (int k = 0; k < 128; k++) {
        float4 bv = *(float4*)&Bs[k * 128 + tx * 4];
#pragma unroll
        for (int i = 0; i < 8; i++) {
            float a = As[(ty * 8 + i) * 128 + k];   // broadcast
            acc[i][0] = fmaf(a, bv.x, acc[i][0]);
            acc[i][1] = fmaf(a, bv.y, acc[i][1]);
            acc[i][2] = fmaf(a, bv.z, acc[i][2]);
            acc[i][3] = fmaf(a, bv.w, acc[i][3]);
        }
    }

    const int n = col0 + tx * 4;
    float4 bb = *(const float4*)&bias[n];
#pragma unroll
    for (int i = 0; i < 8; i++) {
        int r = row0 + ty * 8 + i;
        float4 o4 = make_float4(acc[i][0] + bb.x, acc[i][1] + bb.y,
                                acc[i][2] + bb.z, acc[i][3] + bb.w);
        *(float4*)&g_xk[(size_t)r * FH + n] = o4;
    }
}

// ---------------------------------------------------------------------------
// Kernel C: fused sequential scan.
// 128 CTAs x 512 threads. CTA i handles batch rows (2i, 2i+1).
// Per step: prior rollout, LSTM cell (h@R from L2, xK from scratch),
// posterior heads, generator heads, KL + recon accumulation.
// ---------------------------------------------------------------------------

__device__ __forceinline__ float softplusf(float x) {
    return fmaxf(x, 0.f) + log1pf(expf(-fabsf(x)));
}
__device__ __forceinline__ float sigmoidf(float x) {
    return 1.f / (1.f + expf(-x));
}

// shared memory layout (floats)
#define OFF_WF_M   0
#define OFF_WF_S   4096
#define OFF_WR_M   8192
#define OFF_WR_S   16384
#define OFF_WG_M   24576
#define OFF_WG_S   32768
#define OFF_Z0     40960
#define OFF_Z1     41472
#define OFF_H      41984   // interleaved: h[2k]=row0, h[2k+1]=row1 (256 floats)
#define OFF_M0     42240
#define OFF_M1     42304
#define OFF_MN0    42368
#define OFF_SN0    42432
#define OFF_MN1    42496
#define OFF_SN1    42560
#define OFF_PM0    42624
#define OFF_PS0    42688
#define OFF_PM1    42752
#define OFF_PS1    42816
#define OFF_OM0    42880
#define OFF_OS0    43008
#define OFF_OM1    43136
#define OFF_OS1    43264
#define OFF_BF_M   43392
#define OFF_BF_S   43456
#define OFF_BR_M   43520
#define OFF_BR_S   43584
#define OFF_BG_M   43648
#define OFF_BG_S   43776
#define SCAN_SMEM_FLOATS 43904
#define SCAN_SMEM_BYTES  (SCAN_SMEM_FLOATS * 4)

__global__ void __launch_bounds__(512, 1) scan_kernel(
    const float* __restrict__ obs,
    const float* __restrict__ init_mean,
    const float* __restrict__ Wf_m, const float* __restrict__ bf_m,
    const float* __restrict__ Wf_s, const float* __restrict__ bf_s,
    const float* __restrict__ Wg_m, const float* __restrict__ bg_m,
    const float* __restrict__ Wg_s, const float* __restrict__ bg_s,
    const float* __restrict__ R,
    const float* __restrict__ Wr_m, const float* __restrict__ br_m,
    const float* __restrict__ Wr_s, const float* __restrict__ br_s)
{
    extern __shared__ float smf[];
    const int tid = threadIdx.x;
    const int b0 = 2 * blockIdx.x;
    const int b1 = b0 + 1;

    float* sWf_m = smf + OFF_WF_M;  float* sWf_s = smf + OFF_WF_S;
    float* sWr_m = smf + OFF_WR_M;  float* sWr_s = smf + OFF_WR_S;
    float* sWg_m = smf + OFF_WG_M;  float* sWg_s = smf + OFF_WG_S;
    float* z0s = smf + OFF_Z0;      float* z1s = smf + OFF_Z1;
    float* hs  = smf + OFF_H;
    float* m0  = smf + OFF_M0;      float* m1  = smf + OFF_M1;
    float* mn0 = smf + OFF_MN0;     float* sn0 = smf + OFF_SN0;
    float* mn1 = smf + OFF_MN1;     float* sn1 = smf + OFF_SN1;
    float* pm0 = smf + OFF_PM0;     float* ps0 = smf + OFF_PS0;
    float* pm1 = smf + OFF_PM1;     float* ps1 = smf + OFF_PS1;
    float* om0 = smf + OFF_OM0;     float* os0 = smf + OFF_OS0;
    float* om1 = smf + OFF_OM1;     float* os1 = smf + OFF_OS1;
    float* sbf_m = smf + OFF_BF_M;  float* sbf_s = smf + OFF_BF_S;
    float* sbr_m = smf + OFF_BR_M;  float* sbr_s = smf + OFF_BR_S;
    float* sbg_m = smf + OFF_BG_M;  float* sbg_s = smf + OFF_BG_S;

    // ---- load weights into shared ----
    for (int i = tid; i < SS * SS; i += 512) { sWf_m[i] = Wf_m[i]; sWf_s[i] = Wf_s[i]; }
    for (int i = tid; i < HH * SS; i += 512) { sWr_m[i] = Wr_m[i]; sWr_s[i] = Wr_s[i]; }
    for (int i = tid; i < SS * OO; i += 512) { sWg_m[i] = Wg_m[i]; sWg_s[i] = Wg_s[i]; }
    if (tid < SS) {
        sbf_m[tid] = bf_m[tid]; sbf_s[tid] = bf_s[tid];
        sbr_m[tid] = br_m[tid]; sbr_s[tid] = br_s[tid];
        m0[tid] = init_mean[b0 * SS + tid];
        m1[tid] = init_mean[b1 * SS + tid];
    }
    if (tid < OO) { sbg_m[tid] = bg_m[tid]; sbg_s[tid] = bg_s[tid]; }
    if (tid < 2 * HH) hs[tid] = 0.f;   // h0 = 0 (interleaved rows)
    __syncthreads();

    float c_own = 0.f;       // threads 0..127: c row0[j]; 128..255: c row1[j-128]
    float accLP = 0.f;       // threads 0..255 accumulate logp terms
    float accKL = 0.f;       // threads 256..383 accumulate kl terms

    const size_t xk0_base = (size_t)b0 * TT * FH;
    const size_t xk1_base = (size_t)b1 * TT * FH;

    for (int t = 0; t < TT; t++) {
        // ---- phase 1: z = xK + h @ R  (all 512 threads, one column each) ----
        {
            const int j = tid;
            float acc0 = g_xk[xk0_base + (size_t)t * FH + j];
            float acc1 = g_xk[xk1_base + (size_t)t * FH + j];
            const float* Rj = R + j;
#pragma unroll 8
            for (int k = 0; k < HH; k++) {
                float2 h2 = *(const float2*)&hs[2 * k];
                float r = Rj[(size_t)k * FH];
                acc0 = fmaf(h2.x, r, acc0);
                acc1 = fmaf(h2.y, r, acc1);
            }
            z0s[j] = acc0;
            z1s[j] = acc1;
        }
        __syncthreads();

        // ---- phase 2: gates + prior pre-activations ----
        if (tid < 128) {
            const int j = tid;
            float zi = z0s[j], zf = z0s[128 + j], zg = z0s[256 + j], zo = z0s[384 + j];
            c_own = sigmoidf(zf) * c_own + sigmoidf(zi) * tanhf(zg);
            hs[2 * j] = sigmoidf(zo) * tanhf(c_own);
        } else if (tid < 256) {
            const int j = tid - 128;
            float zi = z1s[j], zf = z1s[128 + j], zg = z1s[256 + j], zo = z1s[384 + j];
            c_own = sigmoidf(zf) * c_own + sigmoidf(zi) * tanhf(zg);
            hs[2 * j + 1] = sigmoidf(zo) * tanhf(c_own);
        } else if (tid < 320) {
            const int s = tid - 256;
            float a = sbf_m[s];
            for (int k = 0; k < SS; k++) a = fmaf(m0[k], sWf_m[k * SS + s], a);
            mn0[s] = a;
        } else if (tid < 384) {
            const int s = tid - 320;
            float a = sbf_s[s];
            for (int k = 0; k < SS; k++) a = fmaf(m0[k], sWf_s[k * SS + s], a);
            sn0[s] = softplusf(a);
        } else if (tid < 448) {
            const int s = tid - 384;
            float a = sbf_m[s];
            for (int k = 0; k < SS; k++) a = fmaf(m1[k], sWf_m[k * SS + s], a);
            mn1[s] = a;
        } else {
            const int s = tid - 448;
            float a = sbf_s[s];
            for (int k = 0; k < SS; k++) a = fmaf(m1[k], sWf_s[k * SS + s], a);
            sn1[s] = softplusf(a);
        }
        __syncthreads();

        // ---- phase 3a: posterior heads + prior mean carry update ----
        if (tid < 64) {
            const int s = tid;
            float a = sbr_m[s];
#pragma unroll 4
            for (int k = 0; k < HH; k++) a = fmaf(hs[2 * k], sWr_m[k * SS + s], a);
            pm0[s] = a;
        } else if (tid < 128) {
            const int s = tid - 64;
            float a = sbr_s[s];
#pragma unroll 4
            for (int k = 0; k < HH; k++) a = fmaf(hs[2 * k], sWr_s[k * SS + s], a);
            ps0[s] = softplusf(a);
        } else if (tid < 192) {
            const int s = tid - 128;
            float a = sbr_m[s];
#pragma unroll 4
            for (int k = 0; k < HH; k++) a = fmaf(hs[2 * k + 1], sWr_m[k * SS + s], a);
            pm1[s] = a;
        } else if (tid < 256) {
            const int s = tid - 192;
            float a = sbr_s[s];
#pragma unroll 4
            for (int k = 0; k < HH; k++) a = fmaf(hs[2 * k + 1], sWr_s[k * SS + s], a);
            ps1[s] = softplusf(a);
        } else if (tid < 320) {
            m0[tid - 256] = mn0[tid - 256];
        } else if (tid < 384) {
            m1[tid - 320] = mn1[tid - 320];
        }
        __syncthreads();

        // ---- phase 3b: generator heads ----
        if (tid < 128) {
            const int o = tid;
            float a = sbg_m[o];
#pragma unroll 4
            for (int k = 0; k < SS; k++) a = fmaf(pm0[k], sWg_m[k * OO + o], a);
            om0[o] = a;
        } else if (tid < 256) {
            const int o = tid - 128;
            float a = sbg_s[o];
#pragma unroll 4
            for (int k = 0; k < SS; k++) a = fmaf(pm0[k], sWg_s[k * OO + o], a);
            os0[o] = softplusf(a);
        } else if (tid < 384) {
            const int o = tid - 256;
            float a = sbg_m[o];
#pragma unroll 4
            for (int k = 0; k < SS; k++) a = fmaf(pm1[k], sWg_m[k * OO + o], a);
            om1[o] = a;
        } else {
            const int o = tid - 384;
            float a = sbg_s[o];
#pragma unroll 4
            for (int k = 0; k < SS; k++) a = fmaf(pm1[k], sWg_s[k * OO + o], a);
            os1[o] = softplusf(a);
        }
        __syncthreads();

        // ---- phase 3c: loss terms ----
        if (tid < 128) {
            const int o = tid;
            float x = obs[((size_t)b0 * TT + t) * OO + o];
            float inv = 1.f / os0[o];
            float d = (x - om0[o]) * inv;
            accLP += -0.5f * d * d - logf(os0[o]) - 0.5f * LOG2PI;
        } else if (tid < 256) {
            const int o = tid - 128;
            float x = obs[((size_t)b1 * TT + t) * OO + o];
            float inv = 1.f / os1[o];
            float d = (x - om1[o]) * inv;
            accLP += -0.5f * d * d - logf(os1[o]) - 0.5f * LOG2PI;
        } else if (tid < 320) {
            const int s = tid - 256;
            float sp = ps0[s], sq = sn0[s];
            float dm = pm0[s] - mn0[s];
            accKL += logf(sq) - logf(sp)
                   + (sp * sp + dm * dm) / (2.f * sq * sq) - 0.5f;
        } else if (tid < 384) {
            const int s = tid - 320;
            float sp = ps1[s], sq = sn1[s];
            float dm = pm1[s] - mn1[s];
            accKL += logf(sq) - logf(sp)
                   + (sp * sp + dm * dm) / (2.f * sq * sq) - 0.5f;
        }
        __syncthreads();
    }

    // ---- block reduction (reuse z buffers) ----
    z0s[tid] = (tid < 256) ? accLP : 0.f;
    z1s[tid] = (tid >= 256 && tid < 384) ? accKL : 0.f;
    __syncthreads();
    for (int s = 256; s > 0; s >>= 1) {
        if (tid < s) {
            z0s[tid] += z0s[tid + s];
            z1s[tid] += z1s[tid + s];
        }
        __syncthreads();
    }
    if (tid == 0) {
        atomicAdd(&g_acc[0], (double)z1s[0]);   // kl
        atomicAdd(&g_acc[1], (double)z0s[0]);   // logp
    }
}

// ---------------------------------------------------------------------------
extern "C" void kernel_launch(void* const* d_in, const int* in_sizes, int n_in,
                              void* d_out, int out_size)
{
    const float* obs       = (const float*)d_in[0];
    const float* init_mean = (const float*)d_in[1];
    /* d_in[2] initial_scale: unused by the reference math */
    const float* Wf_m = (const float*)d_in[3];
    const float* bf_m = (const float*)d_in[4];
    const float* Wf_s = (const float*)d_in[5];
    const float* bf_s = (const float*)d_in[6];
    const float* Wg_m = (const float*)d_in[7];
    const float* bg_m = (const float*)d_in[8];
    const float* Wg_s = (const float*)d_in[9];
    const float* bg_s = (const float*)d_in[10];
    const float* K_lstm = (const float*)d_in[11];
    const float* R_lstm = (const float*)d_in[12];
    const float* b_lstm = (const float*)d_in[13];
    const float* Wr_m = (const float*)d_in[14];
    const float* br_m = (const float*)d_in[15];
    const float* Wr_s = (const float*)d_in[16];
    const float* br_s = (const float*)d_in[17];

    cudaFuncSetAttribute(xk_gemm, cudaFuncAttributeMaxDynamicSharedMemorySize,
                         (64 * 128 + 128 * 128) * 4);
    cudaFuncSetAttribute(scan_kernel, cudaFuncAttributeMaxDynamicSharedMemorySize,
                         SCAN_SMEM_BYTES);

    init_kernel<<<1, 1>>>();

    dim3 ggrid((BB * TT) / 64, FH / 128);
    xk_gemm<<<ggrid, 256, (64 * 128 + 128 * 128) * 4>>>(obs, K_lstm, b_lstm);

    scan_kernel<<<BB / 2, 512, SCAN_SMEM_BYTES>>>(
        obs, init_mean,
        Wf_m, bf_m, Wf_s, bf_s,
        Wg_m, bg_m, Wg_s, bg_s,
        R_lstm,
        Wr_m, br_m, Wr_s, br_s);

    finalize_kernel<<<1, 1>>>((float*)d_out);
}

// round 17
// speedup vs baseline: 2.0332x; 2.0332x over previous
#include <cuda_runtime.h>
#include <math.h>

#define BB 256
#define TT 512
#define SS 64
#define OO 128
#define HH 128
#define FH 512   // 4*H
#define LOG2PI 1.8378770664093453f

typedef unsigned long long ull;

// scratch: xK = obs @ K_lstm + b_lstm   [B*T, 4H]
__device__ float g_xk[(size_t)BB * TT * FH];
__device__ double g_acc[2];   // [0] = sum kl, [1] = sum logp

__global__ void init_kernel() {
    g_acc[0] = 0.0;
    g_acc[1] = 0.0;
}

__global__ void finalize_kernel(float* out) {
    out[0] = (float)(g_acc[0] / (double)(BB * TT) - g_acc[1] / (double)BB);
}

// ---------------- f32x2 helpers ----------------
__device__ __forceinline__ ull pk2(float lo, float hi) {
    ull r; asm("mov.b64 %0, {%1, %2};" : "=l"(r) : "f"(lo), "f"(hi)); return r;
}
__device__ __forceinline__ ull pkd(float v) { return pk2(v, v); }
__device__ __forceinline__ float2 upk2(ull v) {
    float2 r; asm("mov.b64 {%0, %1}, %2;" : "=f"(r.x), "=f"(r.y) : "l"(v)); return r;
}
__device__ __forceinline__ ull ffma2(ull a, ull b, ull c) {
    ull d; asm("fma.rn.f32x2 %0, %1, %2, %3;" : "=l"(d) : "l"(a), "l"(b), "l"(c)); return d;
}
// 2 packed bf16 (in uint32) -> f32x2
__device__ __forceinline__ ull bfpair(unsigned u) {
    return pk2(__uint_as_float(__byte_perm(u, 0u, 0x1044)),
               __uint_as_float(__byte_perm(u, 0u, 0x3244)));
}
__device__ __forceinline__ float bf2f(unsigned short w) {
    return __uint_as_float(((unsigned)w) << 16);
}
__device__ __forceinline__ unsigned short f2bf(float f) {
    unsigned short u; asm("cvt.rn.bf16.f32 %0, %1;" : "=h"(u) : "f"(f)); return u;
}

__device__ __forceinline__ float sigm(float x) {
    return __fdividef(1.f, 1.f + __expf(-x));
}
__device__ __forceinline__ float tanh_f(float x) {
    float ax = fabsf(x);
    float e = __expf(-2.f * ax);
    float r = (1.f - e) * __fdividef(1.f, 1.f + e);
    return copysignf(r, x);
}
__device__ __forceinline__ float splus(float x) {
    return fmaxf(x, 0.f) + __logf(1.f + __expf(-fabsf(x)));
}

// ---------------------------------------------------------------------------
// Kernel A: xk GEMM with FFMA2.  obs [B*T,128] @ K [128,512] + b -> g_xk
// BM=64, BN=128, 256 threads. A stored transposed [k][row] (stride 66).
// Each warp: 8 rows (4 row-pairs) x (lane*4..+3) cols.
// ---------------------------------------------------------------------------
#define AT_STRIDE 66
#define GEMM_SMEM ((128 * AT_STRIDE + 128 * 128) * 4)

__global__ void __launch_bounds__(256) xk_gemm(
    const float* __restrict__ obs,
    const float* __restrict__ K,
    const float* __restrict__ bias)
{
    extern __shared__ float sm[];
    float* At = sm;                       // [128][66]
    float* Bs = sm + 128 * AT_STRIDE;     // [128][128]

    const int row0 = blockIdx.x * 64;
    const int col0 = blockIdx.y * 128;
    const int tid = threadIdx.x;

    // A transposed: At[k][r] = obs[row0+r][k]
    for (int i = tid; i < 64 * 128; i += 256) {
        int r = i >> 7, k = i & 127;
        At[k * AT_STRIDE + r] = obs[(size_t)(row0 + r) * 128 + k];
    }
    // B tile
    for (int i = tid * 4; i < 128 * 128; i += 256 * 4) {
        int k = i >> 7, n = i & 127;
        *(float4*)&Bs[i] = *(const float4*)&K[(size_t)k * FH + col0 + n];
    }
    __syncthreads();

    const int ty = tid >> 5;   // warp -> rows ty*8..+7
    const int tx = tid & 31;   // cols tx*4..+3

    ull acc[4][4];
#pragma unroll
    for (int i = 0; i < 4; i++)
#pragma unroll
        for (int c = 0; c < 4; c++) acc[i][c] = 0ull;

    const int rbase = ty * 8;
#pragma unroll 8
    for (int k = 0; k < 128; k++) {
        float4 bv = *(const float4*)&Bs[k * 128 + tx * 4];
        ull b0 = pkd(bv.x), b1 = pkd(bv.y), b2 = pkd(bv.z), b3 = pkd(bv.w);
#pragma unroll
        for (int i = 0; i < 4; i++) {
            ull a2 = *(const ull*)&At[k * AT_STRIDE + rbase + 2 * i];  // (row 2i, row 2i+1)
            acc[i][0] = ffma2(a2, b0, acc[i][0]);
            acc[i][1] = ffma2(a2, b1, acc[i][1]);
            acc[i][2] = ffma2(a2, b2, acc[i][2]);
            acc[i][3] = ffma2(a2, b3, acc[i][3]);
        }
    }

    float4 bb = *(const float4*)&bias[col0 + tx * 4];
#pragma unroll
    for (int i = 0; i < 4; i++) {
        float2 v0 = upk2(acc[i][0]), v1 = upk2(acc[i][1]);
        float2 v2 = upk2(acc[i][2]), v3 = upk2(acc[i][3]);
        int r0 = row0 + rbase + 2 * i;
        float4 o0 = make_float4(v0.x + bb.x, v1.x + bb.y, v2.x + bb.z, v3.x + bb.w);
        float4 o1 = make_float4(v0.y + bb.x, v1.y + bb.y, v2.y + bb.z, v3.y + bb.w);
        *(float4*)&g_xk[(size_t)r0 * FH + col0 + tx * 4] = o0;
        *(float4*)&g_xk[(size_t)(r0 + 1) * FH + col0 + tx * 4] = o1;
    }
}

// ---------------------------------------------------------------------------
// Kernel C: fused scan, bf16 weights resident in smem, FFMA2 throughout.
// 128 CTAs x 512 threads, 2 batch rows per CTA (packed in f32x2 lanes).
// ---------------------------------------------------------------------------

// byte offsets in dynamic smem
#define OFF_R    0          // 65536 bf16  (131072 B)
#define OFF_WRM  131072     // 8192 bf16
#define OFF_WRS  147456
#define OFF_WGM  163840
#define OFF_WGS  180224
#define OFF_WFM  196608     // 4096 bf16
#define OFF_WFS  204800
#define OFF_Z0   212992     // 512 f
#define OFF_Z1   215040     // 512 f
#define OFF_HD   217088     // 512 f : hd[4k]={h0,h0,h1,h1}
#define OFF_HI   219136     // 256 f : hI[2k]={h0,h1}
#define OFF_MN   220160     // 2 x 128 f (interleaved row pairs, double-buffered)
#define OFF_SN   221184
#define OFF_PM   222208
#define OFF_PS   223232
#define OFF_BFM  224256     // 64 f
#define OFF_BFS  224512
#define OFF_BRM  224768
#define OFF_BRS  225024
#define OFF_BGM  225280     // 128 f
#define OFF_BGS  225792
#define SCAN_SMEM 226304

__global__ void __launch_bounds__(512, 1) scan_kernel(
    const float* __restrict__ obs,
    const float* __restrict__ init_mean,
    const float* __restrict__ Wf_m, const float* __restrict__ bf_m,
    const float* __restrict__ Wf_s, const float* __restrict__ bf_s,
    const float* __restrict__ Wg_m, const float* __restrict__ bg_m,
    const float* __restrict__ Wg_s, const float* __restrict__ bg_s,
    const float* __restrict__ R,
    const float* __restrict__ Wr_m, const float* __restrict__ br_m,
    const float* __restrict__ Wr_s, const float* __restrict__ br_s)
{
    extern __shared__ char smc[];
    unsigned short* sR   = (unsigned short*)(smc + OFF_R);
    unsigned short* sWrm = (unsigned short*)(smc + OFF_WRM);
    unsigned short* sWrs = (unsigned short*)(smc + OFF_WRS);
    unsigned short* sWgm = (unsigned short*)(smc + OFF_WGM);
    unsigned short* sWgs = (unsigned short*)(smc + OFF_WGS);
    unsigned short* sWfm = (unsigned short*)(smc + OFF_WFM);
    unsigned short* sWfs = (unsigned short*)(smc + OFF_WFS);
    float* z0s = (float*)(smc + OFF_Z0);
    float* z1s = (float*)(smc + OFF_Z1);
    float* hd  = (float*)(smc + OFF_HD);
    float* hI  = (float*)(smc + OFF_HI);
    float* mnb = (float*)(smc + OFF_MN);
    float* snb = (float*)(smc + OFF_SN);
    float* pmb = (float*)(smc + OFF_PM);
    float* psb = (float*)(smc + OFF_PS);
    float* sbfm = (float*)(smc + OFF_BFM);
    float* sbfs = (float*)(smc + OFF_BFS);
    float* sbrm = (float*)(smc + OFF_BRM);
    float* sbrs = (float*)(smc + OFF_BRS);
    float* sbgm = (float*)(smc + OFF_BGM);
    float* sbgs = (float*)(smc + OFF_BGS);

    const int tid = threadIdx.x;
    const int b0 = 2 * blockIdx.x;
    const int b1 = b0 + 1;

    // ---- convert weights fp32 -> bf16 into smem ----
    for (int i = tid; i < HH * FH; i += 512) sR[i] = f2bf(R[i]);
    for (int i = tid; i < HH * SS; i += 512) { sWrm[i] = f2bf(Wr_m[i]); sWrs[i] = f2bf(Wr_s[i]); }
    for (int i = tid; i < SS * OO; i += 512) { sWgm[i] = f2bf(Wg_m[i]); sWgs[i] = f2bf(Wg_s[i]); }
    for (int i = tid; i < SS * SS; i += 512) { sWfm[i] = f2bf(Wf_m[i]); sWfs[i] = f2bf(Wf_s[i]); }
    if (tid < SS) {
        sbfm[tid] = bf_m[tid]; sbfs[tid] = bf_s[tid];
        sbrm[tid] = br_m[tid]; sbrs[tid] = br_s[tid];
        // mn buffer 1 seeds prior at t=0 with initial_mean
        mnb[128 + 2 * tid]     = init_mean[b0 * SS + tid];
        mnb[128 + 2 * tid + 1] = init_mean[b1 * SS + tid];
    }
    if (tid < OO) { sbgm[tid] = bg_m[tid]; sbgs[tid] = bg_s[tid]; }
    if (tid < 512) hd[tid] = 0.f;
    if (tid < 256) hI[tid] = 0.f;
    __syncthreads();

    float c_reg = 0.f;    // gate threads: cell state
    float accLP = 0.f;    // tid 256..383
    float accKL = 0.f;    // tid 384..447

    const float* xk0 = g_xk + (size_t)b0 * TT * FH;
    const float* xk1 = g_xk + (size_t)b1 * TT * FH;

    for (int t = 0; t <= TT; t++) {
        const int cur = t & 1, prv = cur ^ 1;

        // =========================== S1 ===========================
        if (tid < 128) {                       // z = xk + h @ R  (bf16 R, f32x2)
            if (t < TT) {
                const int jg = tid * 4;
                float4 x0 = *(const float4*)(xk0 + (size_t)t * FH + jg);
                float4 x1 = *(const float4*)(xk1 + (size_t)t * FH + jg);
                ull a00 = pk2(x0.x, x0.y), a01 = pk2(x0.z, x0.w);
                ull a10 = pk2(x1.x, x1.y), a11 = pk2(x1.z, x1.w);
#pragma unroll 8
                for (int k = 0; k < HH; k++) {
                    uint2 rv = *(const uint2*)(sR + k * FH + jg);
                    ull r01 = bfpair(rv.x);
                    ull r23 = bfpair(rv.y);
                    ulonglong2 hv = *(const ulonglong2*)(hd + 4 * k); // x=(h0,h0) y=(h1,h1)
                    a00 = ffma2(r01, hv.x, a00);
                    a01 = ffma2(r23, hv.x, a01);
                    a10 = ffma2(r01, hv.y, a10);
                    a11 = ffma2(r23, hv.y, a11);
                }
                *(ull*)(z0s + jg)     = a00;  *(ull*)(z0s + jg + 2) = a01;
                *(ull*)(z1s + jg)     = a10;  *(ull*)(z1s + jg + 2) = a11;
            }
        } else if (tid < 256) {                // prior rollout (t)
            if (t < TT) {
                const int l = tid - 128;
                const int s = l & 63, head = l >> 6;
                const unsigned short* W = head ? sWfs : sWfm;
                ull acc = pkd(head ? sbfs[s] : sbfm[s]);
                const float* mp = mnb + 128 * prv;
#pragma unroll 16
                for (int k = 0; k < SS; k++) {
                    float w = bf2f(W[k * SS + s]);
                    ull m2 = *(const ull*)(mp + 2 * k);
                    acc = ffma2(pkd(w), m2, acc);
                }
                if (head) {
                    float2 v = upk2(acc);
                    *(ull*)(snb + 128 * cur + 2 * s) = pk2(splus(v.x), splus(v.y));
                } else {
                    *(ull*)(mnb + 128 * cur + 2 * s) = acc;
                }
            }
        } else if (tid < 384) {                // generator + recon (t-1)
            if (t > 0) {
                const int o = tid - 256;
                ull am = pkd(sbgm[o]);
                ull as_ = pkd(sbgs[o]);
                const float* pp = pmb + 128 * prv;
#pragma unroll 16
                for (int k = 0; k < SS; k++) {
                    float wm = bf2f(sWgm[k * OO + o]);
                    float ws = bf2f(sWgs[k * OO + o]);
                    ull p2 = *(const ull*)(pp + 2 * k);
                    am  = ffma2(pkd(wm), p2, am);
                    as_ = ffma2(pkd(ws), p2, as_);
                }
                float2 om = upk2(am), osr = upk2(as_);
                float os0 = splus(osr.x), os1 = splus(osr.y);
                float x0 = obs[((size_t)b0 * TT + (t - 1)) * OO + o];
                float x1 = obs[((size_t)b1 * TT + (t - 1)) * OO + o];
                float d0 = (x0 - om.x) * __fdividef(1.f, os0);
                float d1 = (x1 - om.y) * __fdividef(1.f, os1);
                accLP += -0.5f * d0 * d0 - __logf(os0) - 0.5f * LOG2PI
                       + -0.5f * d1 * d1 - __logf(os1) - 0.5f * LOG2PI;
            }
        } else if (tid < 448) {                // KL (t-1)
            if (t > 0) {
                const int s = tid - 384;
                const float* pm_ = pmb + 128 * prv + 2 * s;
                const float* ps_ = psb + 128 * prv + 2 * s;
                const float* mn_ = mnb + 128 * prv + 2 * s;
                const float* sn_ = snb + 128 * prv + 2 * s;
#pragma unroll
                for (int r = 0; r < 2; r++) {
                    float sp = ps_[r], sq = sn_[r];
                    float dm = pm_[r] - mn_[r];
                    float rq = __fdividef(1.f, sq);
                    accKL += __logf(sq) - __logf(sp)
                           + (sp * sp + dm * dm) * 0.5f * rq * rq - 0.5f;
                }
            }
        }
        __syncthreads();

        // =========================== S2: gates ===========================
        if (t < TT && tid < 256) {
            const int j = tid & 127, row = tid >> 7;
            const float* z = row ? z1s : z0s;
            float zi = z[j], zf = z[j + 128], zg = z[j + 256], zo = z[j + 384];
            c_reg = sigm(zf) * c_reg + sigm(zi) * tanh_f(zg);
            float h = sigm(zo) * tanh_f(c_reg);
            *(float2*)(hd + 4 * j + 2 * row) = make_float2(h, h);
            hI[2 * j + row] = h;
        }
        __syncthreads();

        // =========================== S3: posterior ===========================
        if (t < TT && tid < 128) {
            const int s = tid & 63, head = tid >> 6;
            const unsigned short* W = head ? sWrs : sWrm;
            ull acc = pkd(head ? sbrs[s] : sbrm[s]);
#pragma unroll 16
            for (int k = 0; k < HH; k++) {
                float w = bf2f(W[k * SS + s]);
                ull h2 = *(const ull*)(hI + 2 * k);
                acc = ffma2(pkd(w), h2, acc);
            }
            if (head) {
                float2 v = upk2(acc);
                *(ull*)(psb + 128 * cur + 2 * s) = pk2(splus(v.x), splus(v.y));
            } else {
                *(ull*)(pmb + 128 * cur + 2 * s) = acc;
            }
        }
        __syncthreads();
    }

    // ---- block reduction ----
    z0s[tid] = (tid >= 256 && tid < 384) ? accLP : 0.f;
    z1s[tid] = (tid >= 384 && tid < 448) ? accKL : 0.f;
    __syncthreads();
    for (int s = 256; s > 0; s >>= 1) {
        if (tid < s) {
            z0s[tid] += z0s[tid + s];
            z1s[tid] += z1s[tid + s];
        }
        __syncthreads();
    }
    if (tid == 0) {
        atomicAdd(&g_acc[0], (double)z1s[0]);   // kl
        atomicAdd(&g_acc[1], (double)z0s[0]);   // logp
    }
}

// ---------------------------------------------------------------------------
extern "C" void kernel_launch(void* const* d_in, const int* in_sizes, int n_in,
                              void* d_out, int out_size)
{
    const float* obs       = (const float*)d_in[0];
    const float* init_mean = (const float*)d_in[1];
    /* d_in[2] initial_scale: unused by the reference math */
    const float* Wf_m = (const float*)d_in[3];
    const float* bf_m = (const float*)d_in[4];
    const float* Wf_s = (const float*)d_in[5];
    const float* bf_s = (const float*)d_in[6];
    const float* Wg_m = (const float*)d_in[7];
    const float* bg_m = (const float*)d_in[8];
    const float* Wg_s = (const float*)d_in[9];
    const float* bg_s = (const float*)d_in[10];
    const float* K_lstm = (const float*)d_in[11];
    const float* R_lstm = (const float*)d_in[12];
    const float* b_lstm = (const float*)d_in[13];
    const float* Wr_m = (const float*)d_in[14];
    const float* br_m = (const float*)d_in[15];
    const float* Wr_s = (const float*)d_in[16];
    const float* br_s = (const float*)d_in[17];

    cudaFuncSetAttribute(xk_gemm, cudaFuncAttributeMaxDynamicSharedMemorySize, GEMM_SMEM);
    cudaFuncSetAttribute(scan_kernel, cudaFuncAttributeMaxDynamicSharedMemorySize, SCAN_SMEM);

    init_kernel<<<1, 1>>>();

    dim3 ggrid((BB * TT) / 64, FH / 128);
    xk_gemm<<<ggrid, 256, GEMM_SMEM>>>(obs, K_lstm, b_lstm);

    scan_kernel<<<BB / 2, 512, SCAN_SMEM>>>(
        obs, init_mean,
        Wf_m, bf_m, Wf_s, bf_s,
        Wg_m, bg_m, Wg_s, bg_s,
        R_lstm,
        Wr_m, br_m, Wr_s, br_s);

    finalize_kernel<<<1, 1>>>((float*)d_out);
}